// round 12
// baseline (speedup 1.0000x reference)
#include <cuda_runtime.h>
#include <mma.h>
#include <cstdint>

using namespace nvcuda;

#define NN 100000
#define NE 1600000
#define NP 500000
#define D  128
#define BP 132   // scalar-GEMM smem pitch
#define LT  68   // float pitch, K=64 chunk tiles (wmma)
#define LF  132  // float pitch, K=128 tiles / staging (wmma)

// ---------------- tf32 split helpers ----------------
__device__ __forceinline__ void split_tf(float v, float& h, float& l) {
    h = wmma::__float_to_tf32(v);
    l = v - h;
}
__device__ __forceinline__ void split4(float4 v, float4& h, float4& l) {
    split_tf(v.x, h.x, l.x); split_tf(v.y, h.y, l.y);
    split_tf(v.z, h.z, l.z); split_tf(v.w, h.w, l.w);
}

// ---------------- scratch ----------------
__device__ int   g_cnt[NN];
__device__ int   g_rowptr[NN + 1];
__device__ int   g_pos[NN];
__device__ float g_inv[NN];
__device__ int   g_srcs[NE];
__device__ float g_aggr[(size_t)NN * D];
__device__ float g_h[(size_t)NN * D];
__device__ float g_z[(size_t)NN * D];
__device__ float g_wt1[256 * 128];   // [Wl|Wr] layer1, k-major: [k][j]
__device__ float g_wt2[256 * 128];   // layer2

// ---------------- CSR build ----------------
__global__ void k_zero() {
    int i = blockIdx.x * blockDim.x + threadIdx.x;
    if (i < NN) g_cnt[i] = 0;
}
__global__ void k_count(const int* __restrict__ ei) {
    int i = blockIdx.x * blockDim.x + threadIdx.x;
    if (i < NE) atomicAdd(&g_cnt[ei[NE + i]], 1);
}
__global__ void k_scan() {
    __shared__ int s[1024];
    int tid = threadIdx.x;
    int base = 0;
    for (int start = 0; start < NN; start += 1024) {
        int i = start + tid;
        int v = (i < NN) ? g_cnt[i] : 0;
        s[tid] = v;
        __syncthreads();
        for (int off = 1; off < 1024; off <<= 1) {
            int t = (tid >= off) ? s[tid - off] : 0;
            __syncthreads();
            s[tid] += t;
            __syncthreads();
        }
        int excl = base + s[tid] - v;
        if (i < NN) {
            g_rowptr[i] = excl;
            g_pos[i]    = excl;
            g_inv[i]    = 1.0f / (float)(v > 0 ? v : 1);
        }
        base += s[1023];
        __syncthreads();
    }
    if (tid == 0) g_rowptr[NN] = base;
}
__global__ void k_scatter(const int* __restrict__ ei) {
    int i = blockIdx.x * blockDim.x + threadIdx.x;
    if (i < NE) {
        int dst = ei[NE + i];
        int src = ei[i];
        int p = atomicAdd(&g_pos[dst], 1);
        g_srcs[p] = src;
    }
}

// ---------------- weight transpose for scalar layer GEMM ----------------
__global__ void k_wt(const float* __restrict__ W1l, const float* __restrict__ W1r,
                     const float* __restrict__ W2l, const float* __restrict__ W2r) {
    int i = blockIdx.x * blockDim.x + threadIdx.x;
    if (i < 256 * 128) {
        int k = i >> 7, j = i & 127;
        g_wt1[i] = (k < 128) ? W1l[j * 128 + k] : W1r[j * 128 + (k - 128)];
        g_wt2[i] = (k < 128) ? W2l[j * 128 + k] : W2r[j * 128 + (k - 128)];
    }
}

// ---------------- mean aggregation ----------------
__global__ void k_aggr(const float* __restrict__ x, int layer) {
    const float* __restrict__ feat = (layer == 1) ? x : g_h;
    int warp = (blockIdx.x * blockDim.x + threadIdx.x) >> 5;
    int lane = threadIdx.x & 31;
    if (warp >= NN) return;
    int beg = g_rowptr[warp], end = g_rowptr[warp + 1];
    float4 acc = make_float4(0.f, 0.f, 0.f, 0.f);
    for (int e = beg; e < end; e++) {
        int s = g_srcs[e];
        float4 v = *(const float4*)&feat[(size_t)s * D + lane * 4];
        acc.x += v.x; acc.y += v.y; acc.z += v.z; acc.w += v.w;
    }
    float inv = g_inv[warp];
    acc.x *= inv; acc.y *= inv; acc.z *= inv; acc.w *= inv;
    *(float4*)&g_aggr[(size_t)warp * D + lane * 4] = acc;
}

// ---------------- layer GEMM: PROVEN scalar FFMA version (Round 3) ----------------
__global__ void __launch_bounds__(256, 1)
k_gemm_layer(const float* __restrict__ x, const float* __restrict__ bias, int layer) {
    extern __shared__ float sm[];
    float* Bs = sm;               // [256][BP]
    float* As = sm + 256 * BP;    // [32][BP]

    const float* __restrict__ Aself = (layer == 1) ? x : g_h;
    const float* __restrict__ Wt    = (layer == 1) ? g_wt1 : g_wt2;
    float* __restrict__ out         = (layer == 1) ? g_h : g_z;
    const int do_relu = (layer == 1);

    int tid = threadIdx.x;
    int tx = tid & 15, ty = tid >> 4;
    int row0 = blockIdx.x * 128;

    for (int idx = tid * 4; idx < 256 * 128; idx += 256 * 4) {
        int k = idx >> 7, j = idx & 127;
        *(float4*)&Bs[k * BP + j] = *(const float4*)&Wt[idx];
    }
    float bj[8];
#pragma unroll
    for (int j = 0; j < 8; j++) bj[j] = bias[tx * 8 + j];

    float acc[8][8];
#pragma unroll
    for (int i = 0; i < 8; i++)
#pragma unroll
        for (int j = 0; j < 8; j++) acc[i][j] = 0.f;

    __syncthreads();

    for (int kk = 0; kk < 256; kk += 32) {
        const float* __restrict__ A = (kk < 128) ? g_aggr : Aself;
        int kb = kk & 127;
#pragma unroll
        for (int l = 0; l < 4; l++) {
            int idx = tid + l * 256;
            int r = idx >> 3, kq = idx & 7;
            int row = row0 + r;
            float4 v = make_float4(0.f, 0.f, 0.f, 0.f);
            if (row < NN) v = *(const float4*)&A[(size_t)row * 128 + kb + kq * 4];
            As[(kq * 4 + 0) * BP + r] = v.x;
            As[(kq * 4 + 1) * BP + r] = v.y;
            As[(kq * 4 + 2) * BP + r] = v.z;
            As[(kq * 4 + 3) * BP + r] = v.w;
        }
        __syncthreads();
#pragma unroll 8
        for (int k = 0; k < 32; k++) {
            float4 a0 = *(float4*)&As[k * BP + ty * 8];
            float4 a1 = *(float4*)&As[k * BP + ty * 8 + 4];
            float4 b0 = *(float4*)&Bs[(kk + k) * BP + tx * 8];
            float4 b1 = *(float4*)&Bs[(kk + k) * BP + tx * 8 + 4];
            float a[8] = {a0.x, a0.y, a0.z, a0.w, a1.x, a1.y, a1.z, a1.w};
            float b[8] = {b0.x, b0.y, b0.z, b0.w, b1.x, b1.y, b1.z, b1.w};
#pragma unroll
            for (int i = 0; i < 8; i++)
#pragma unroll
                for (int j = 0; j < 8; j++) acc[i][j] += a[i] * b[j];
        }
        __syncthreads();
    }

#pragma unroll
    for (int i = 0; i < 8; i++) {
        int row = row0 + ty * 8 + i;
        if (row < NN) {
            float o[8];
#pragma unroll
            for (int j = 0; j < 8; j++) {
                float v = acc[i][j] + bj[j];
                o[j] = do_relu ? fmaxf(v, 0.f) : v;
            }
            *(float4*)&out[(size_t)row * 128 + tx * 8]     = make_float4(o[0], o[1], o[2], o[3]);
            *(float4*)&out[(size_t)row * 128 + tx * 8 + 4] = make_float4(o[4], o[5], o[6], o[7]);
        }
    }
}

// ================= decoder: tf32 wmma (Round-9 version, under test) =================
#define DC_AH  0
#define DC_AL  67584
#define DC_B   135168
#define DC_SMEM 204800

__global__ void __launch_bounds__(256, 1)
k_decoder(const int* __restrict__ pairs,
          const float* __restrict__ Wm1, const float* __restrict__ bm1,
          const float* __restrict__ Wm2, const float* __restrict__ bm2,
          const float* __restrict__ wm3, const float* __restrict__ bm3,
          float* __restrict__ out) {
    extern __shared__ char smc[];
    float* Ah  = (float*)(smc + DC_AH);
    float* Al  = (float*)(smc + DC_AL);
    float* B1h = (float*)(smc + DC_B);
    float* B1l = (float*)(smc + DC_B + 34816);
    float* Sg  = (float*)(smc + DC_B);
    float* B2h = (float*)(smc + DC_B);
    float* B2l = (float*)(smc + DC_B + 33792);
    int tid = threadIdx.x, wid = tid >> 5;
    int p0 = blockIdx.x * 128;
    int m0 = wid * 16;

    // hp = z[i0]*z[i1] -> split-tf32 A (full K=128)
    {
        int p = tid >> 1;
        int d0 = (tid & 1) * 64;
        int pg = p0 + p;
        if (pg >= NP) pg = 0;
        int i0 = pairs[(size_t)pg * 2 + 0];
        int i1 = pairs[(size_t)pg * 2 + 1];
        const float* z0 = &g_z[(size_t)i0 * 128 + d0];
        const float* z1 = &g_z[(size_t)i1 * 128 + d0];
#pragma unroll
        for (int t = 0; t < 16; t++) {
            float4 a = *(const float4*)&z0[t * 4];
            float4 b = *(const float4*)&z1[t * 4];
            float4 v = make_float4(a.x * b.x, a.y * b.y, a.z * b.z, a.w * b.w);
            float4 h, l;
            split4(v, h, l);
            *(float4*)&Ah[p * LF + d0 + t * 4] = h;
            *(float4*)&Al[p * LF + d0 + t * 4] = l;
        }
    }

    // GEMM1: t1 = hp @ Wm1^T  (K=128, chunked by 64 for B1)
    wmma::fragment<wmma::accumulator, 16, 16, 8, float> acc1[8];
#pragma unroll
    for (int jt = 0; jt < 8; jt++) wmma::fill_fragment(acc1[jt], 0.f);
    for (int c = 0; c < 2; c++) {
        int ka = c * 64;
        for (int idx = tid * 4; idx < 128 * 64; idx += 1024) {
            int j = idx >> 6, k = idx & 63;
            float4 v = *(const float4*)&Wm1[j * 128 + ka + k];
            float4 h, l;
            split4(v, h, l);
            *(float4*)&B1h[j * LT + k] = h;
            *(float4*)&B1l[j * LT + k] = l;
        }
        __syncthreads();
        for (int kk = 0; kk < 64; kk += 8) {
            wmma::fragment<wmma::matrix_a, 16, 16, 8, wmma::precision::tf32, wmma::row_major> ah, al;
            wmma::load_matrix_sync(ah, Ah + m0 * LF + ka + kk, LF);
            wmma::load_matrix_sync(al, Al + m0 * LF + ka + kk, LF);
#pragma unroll
            for (int jt = 0; jt < 8; jt++) {
                wmma::fragment<wmma::matrix_b, 16, 16, 8, wmma::precision::tf32, wmma::col_major> bh, bl;
                wmma::load_matrix_sync(bh, B1h + jt * 16 * LT + kk, LT);
                wmma::load_matrix_sync(bl, B1l + jt * 16 * LT + kk, LT);
                wmma::mma_sync(acc1[jt], ah, bh, acc1[jt]);
                wmma::mma_sync(acc1[jt], ah, bl, acc1[jt]);
                wmma::mma_sync(acc1[jt], al, bh, acc1[jt]);
            }
        }
        __syncthreads();
    }

#pragma unroll
    for (int jt = 0; jt < 8; jt++)
        wmma::store_matrix_sync(Sg + m0 * LF + jt * 16, acc1[jt], LF, wmma::mem_row_major);
    __syncthreads();

    // t1 = relu(Sg + bm1) -> re-split into A
    for (int idx = tid * 4; idx < 128 * 128; idx += 1024) {
        int r = idx >> 7, k = idx & 127;
        float4 b = *(const float4*)&bm1[k];
        float4 s = *(float4*)&Sg[r * LF + k];
        float4 v = make_float4(fmaxf(s.x + b.x, 0.f), fmaxf(s.y + b.y, 0.f),
                               fmaxf(s.z + b.z, 0.f), fmaxf(s.w + b.w, 0.f));
        float4 h, l;
        split4(v, h, l);
        *(float4*)&Ah[r * LF + k] = h;
        *(float4*)&Al[r * LF + k] = l;
    }
    __syncthreads();

    // stage B2 = Wm2 [64][128] full K
    for (int idx = tid * 4; idx < 64 * 128; idx += 1024) {
        int j = idx >> 7, k = idx & 127;
        float4 v = *(const float4*)&Wm2[j * 128 + k];
        float4 h, l;
        split4(v, h, l);
        *(float4*)&B2h[j * LF + k] = h;
        *(float4*)&B2l[j * LF + k] = l;
    }
    __syncthreads();

    // GEMM2: t2 = t1 @ Wm2^T  (128x64, K=128)
    wmma::fragment<wmma::accumulator, 16, 16, 8, float> acc2[4];
#pragma unroll
    for (int jt = 0; jt < 4; jt++) wmma::fill_fragment(acc2[jt], 0.f);
    for (int kk = 0; kk < 128; kk += 8) {
        wmma::fragment<wmma::matrix_a, 16, 16, 8, wmma::precision::tf32, wmma::row_major> ah, al;
        wmma::load_matrix_sync(ah, Ah + m0 * LF + kk, LF);
        wmma::load_matrix_sync(al, Al + m0 * LF + kk, LF);
#pragma unroll
        for (int jt = 0; jt < 4; jt++) {
            wmma::fragment<wmma::matrix_b, 16, 16, 8, wmma::precision::tf32, wmma::col_major> bh, bl;
            wmma::load_matrix_sync(bh, B2h + jt * 16 * LF + kk, LF);
            wmma::load_matrix_sync(bl, B2l + jt * 16 * LF + kk, LF);
            wmma::mma_sync(acc2[jt], ah, bh, acc2[jt]);
            wmma::mma_sync(acc2[jt], ah, bl, acc2[jt]);
            wmma::mma_sync(acc2[jt], al, bh, acc2[jt]);
        }
    }
    __syncthreads();
#pragma unroll
    for (int jt = 0; jt < 4; jt++)
        wmma::store_matrix_sync(Sg + m0 * LT + jt * 16, acc2[jt], LT, wmma::mem_row_major);
    __syncthreads();

    if (tid < 128) {
        int p = p0 + tid;
        float acc = bm3[0];
#pragma unroll 16
        for (int j = 0; j < 64; j++)
            acc += fmaxf(Sg[tid * LT + j] + bm2[j], 0.f) * wm3[j];
        if (p < NP) out[p] = acc;
    }
}

// ================= launch =================
extern "C" void kernel_launch(void* const* d_in, const int* in_sizes, int n_in,
                              void* d_out, int out_size) {
    const float* x     = (const float*)d_in[0];
    const int*   ei    = (const int*)d_in[1];
    const int*   pairs = (const int*)d_in[2];
    const float* W1l = (const float*)d_in[3];
    const float* b1l = (const float*)d_in[4];
    const float* W1r = (const float*)d_in[5];
    const float* W2l = (const float*)d_in[6];
    const float* b2l = (const float*)d_in[7];
    const float* W2r = (const float*)d_in[8];
    const float* Wm1 = (const float*)d_in[9];
    const float* bm1 = (const float*)d_in[10];
    const float* Wm2 = (const float*)d_in[11];
    const float* bm2 = (const float*)d_in[12];
    const float* Wm3 = (const float*)d_in[13];
    const float* bm3 = (const float*)d_in[14];
    float* out = (float*)d_out;
    (void)in_sizes; (void)n_in; (void)out_size;

    size_t smem_layer = (size_t)(256 + 32) * BP * sizeof(float);   // 152064
    cudaFuncSetAttribute(k_gemm_layer, cudaFuncAttributeMaxDynamicSharedMemorySize, (int)smem_layer);
    cudaFuncSetAttribute(k_decoder,    cudaFuncAttributeMaxDynamicSharedMemorySize, DC_SMEM);

    // CSR build
    k_zero<<<(NN + 255) / 256, 256>>>();
    k_count<<<(NE + 255) / 256, 256>>>(ei);
    k_scan<<<1, 1024>>>();
    k_scatter<<<(NE + 255) / 256, 256>>>(ei);
    k_wt<<<(256 * 128 + 255) / 256, 256>>>(W1l, W1r, W2l, W2r);

    // layer 1
    k_aggr<<<(NN * 32 + 255) / 256, 256>>>(x, 1);
    k_gemm_layer<<<(NN + 127) / 128, 256, smem_layer>>>(x, b1l, 1);
    // layer 2
    k_aggr<<<(NN * 32 + 255) / 256, 256>>>(x, 2);
    k_gemm_layer<<<(NN + 127) / 128, 256, smem_layer>>>(g_h, b2l, 2);
    // decoder (tf32 wmma — under test)
    k_decoder<<<(NP + 127) / 128, 256, DC_SMEM>>>(pairs, Wm1, bm1, Wm2, bm2, Wm3, bm3, out);
}

// round 13
// speedup vs baseline: 1.5547x; 1.5547x over previous
#include <cuda_runtime.h>
#include <cuda_fp16.h>
#include <mma.h>
#include <cstdint>

using namespace nvcuda;

#define NN 100000
#define NE 1600000
#define NP 500000
#define D  128
#define BP 132   // scalar-GEMM smem pitch
#define LH 136   // half pitch for fp16 tiles (272B rows; LDSM conflict-free)
#define LF 132   // float pitch for staging
#define LT 68    // float pitch for final staging

// ---------------- fp16 split helpers ----------------
__device__ __forceinline__ void split4h(float4 v, uint2& hq, uint2& lq) {
    __half h0 = __float2half_rn(v.x), h1 = __float2half_rn(v.y);
    __half h2 = __float2half_rn(v.z), h3 = __float2half_rn(v.w);
    __half l0 = __float2half_rn(v.x - __half2float(h0));
    __half l1 = __float2half_rn(v.y - __half2float(h1));
    __half l2 = __float2half_rn(v.z - __half2float(h2));
    __half l3 = __float2half_rn(v.w - __half2float(h3));
    hq.x = (uint32_t)__half_as_ushort(h0) | ((uint32_t)__half_as_ushort(h1) << 16);
    hq.y = (uint32_t)__half_as_ushort(h2) | ((uint32_t)__half_as_ushort(h3) << 16);
    lq.x = (uint32_t)__half_as_ushort(l0) | ((uint32_t)__half_as_ushort(l1) << 16);
    lq.y = (uint32_t)__half_as_ushort(l2) | ((uint32_t)__half_as_ushort(l3) << 16);
}

// ---------------- scratch ----------------
__device__ int   g_cnt[NN];
__device__ int   g_rowptr[NN + 1];
__device__ int   g_pos[NN];
__device__ float g_inv[NN];
__device__ int   g_srcs[NE];
__device__ float g_aggr[(size_t)NN * D];
__device__ float g_h[(size_t)NN * D];
__device__ float g_z[(size_t)NN * D];
__device__ float g_wt1[256 * 128];
__device__ float g_wt2[256 * 128];

// ---------------- CSR build ----------------
__global__ void k_zero() {
    int i = blockIdx.x * blockDim.x + threadIdx.x;
    if (i < NN) g_cnt[i] = 0;
}
__global__ void k_count(const int* __restrict__ ei) {
    int i = blockIdx.x * blockDim.x + threadIdx.x;
    if (i < NE) atomicAdd(&g_cnt[ei[NE + i]], 1);
}
__global__ void k_scan() {
    __shared__ int s[1024];
    int tid = threadIdx.x;
    int base = 0;
    for (int start = 0; start < NN; start += 1024) {
        int i = start + tid;
        int v = (i < NN) ? g_cnt[i] : 0;
        s[tid] = v;
        __syncthreads();
        for (int off = 1; off < 1024; off <<= 1) {
            int t = (tid >= off) ? s[tid - off] : 0;
            __syncthreads();
            s[tid] += t;
            __syncthreads();
        }
        int excl = base + s[tid] - v;
        if (i < NN) {
            g_rowptr[i] = excl;
            g_pos[i]    = excl;
            g_inv[i]    = 1.0f / (float)(v > 0 ? v : 1);
        }
        base += s[1023];
        __syncthreads();
    }
    if (tid == 0) g_rowptr[NN] = base;
}
__global__ void k_scatter(const int* __restrict__ ei) {
    int i = blockIdx.x * blockDim.x + threadIdx.x;
    if (i < NE) {
        int dst = ei[NE + i];
        int src = ei[i];
        int p = atomicAdd(&g_pos[dst], 1);
        g_srcs[p] = src;
    }
}

// ---------------- weight transpose (scalar layer GEMM) ----------------
__global__ void k_wt(const float* __restrict__ W1l, const float* __restrict__ W1r,
                     const float* __restrict__ W2l, const float* __restrict__ W2r) {
    int i = blockIdx.x * blockDim.x + threadIdx.x;
    if (i < 256 * 128) {
        int k = i >> 7, j = i & 127;
        g_wt1[i] = (k < 128) ? W1l[j * 128 + k] : W1r[j * 128 + (k - 128)];
        g_wt2[i] = (k < 128) ? W2l[j * 128 + k] : W2r[j * 128 + (k - 128)];
    }
}

// ---------------- mean aggregation ----------------
__global__ void k_aggr(const float* __restrict__ x, int layer) {
    const float* __restrict__ feat = (layer == 1) ? x : g_h;
    int warp = (blockIdx.x * blockDim.x + threadIdx.x) >> 5;
    int lane = threadIdx.x & 31;
    if (warp >= NN) return;
    int beg = g_rowptr[warp], end = g_rowptr[warp + 1];
    float4 acc = make_float4(0.f, 0.f, 0.f, 0.f);
    for (int e = beg; e < end; e++) {
        int s = g_srcs[e];
        float4 v = *(const float4*)&feat[(size_t)s * D + lane * 4];
        acc.x += v.x; acc.y += v.y; acc.z += v.z; acc.w += v.w;
    }
    float inv = g_inv[warp];
    acc.x *= inv; acc.y *= inv; acc.z *= inv; acc.w *= inv;
    *(float4*)&g_aggr[(size_t)warp * D + lane * 4] = acc;
}

// ---------------- layer GEMM: PROVEN scalar FFMA (Round 3) ----------------
__global__ void __launch_bounds__(256, 1)
k_gemm_layer(const float* __restrict__ x, const float* __restrict__ bias, int layer) {
    extern __shared__ float sm[];
    float* Bs = sm;               // [256][BP]
    float* As = sm + 256 * BP;    // [32][BP]

    const float* __restrict__ Aself = (layer == 1) ? x : g_h;
    const float* __restrict__ Wt    = (layer == 1) ? g_wt1 : g_wt2;
    float* __restrict__ out         = (layer == 1) ? g_h : g_z;
    const int do_relu = (layer == 1);

    int tid = threadIdx.x;
    int tx = tid & 15, ty = tid >> 4;
    int row0 = blockIdx.x * 128;

    for (int idx = tid * 4; idx < 256 * 128; idx += 256 * 4) {
        int k = idx >> 7, j = idx & 127;
        *(float4*)&Bs[k * BP + j] = *(const float4*)&Wt[idx];
    }
    float bj[8];
#pragma unroll
    for (int j = 0; j < 8; j++) bj[j] = bias[tx * 8 + j];

    float acc[8][8];
#pragma unroll
    for (int i = 0; i < 8; i++)
#pragma unroll
        for (int j = 0; j < 8; j++) acc[i][j] = 0.f;

    __syncthreads();

    for (int kk = 0; kk < 256; kk += 32) {
        const float* __restrict__ A = (kk < 128) ? g_aggr : Aself;
        int kb = kk & 127;
#pragma unroll
        for (int l = 0; l < 4; l++) {
            int idx = tid + l * 256;
            int r = idx >> 3, kq = idx & 7;
            int row = row0 + r;
            float4 v = make_float4(0.f, 0.f, 0.f, 0.f);
            if (row < NN) v = *(const float4*)&A[(size_t)row * 128 + kb + kq * 4];
            As[(kq * 4 + 0) * BP + r] = v.x;
            As[(kq * 4 + 1) * BP + r] = v.y;
            As[(kq * 4 + 2) * BP + r] = v.z;
            As[(kq * 4 + 3) * BP + r] = v.w;
        }
        __syncthreads();
#pragma unroll 8
        for (int k = 0; k < 32; k++) {
            float4 a0 = *(float4*)&As[k * BP + ty * 8];
            float4 a1 = *(float4*)&As[k * BP + ty * 8 + 4];
            float4 b0 = *(float4*)&Bs[(kk + k) * BP + tx * 8];
            float4 b1 = *(float4*)&Bs[(kk + k) * BP + tx * 8 + 4];
            float a[8] = {a0.x, a0.y, a0.z, a0.w, a1.x, a1.y, a1.z, a1.w};
            float b[8] = {b0.x, b0.y, b0.z, b0.w, b1.x, b1.y, b1.z, b1.w};
#pragma unroll
            for (int i = 0; i < 8; i++)
#pragma unroll
                for (int j = 0; j < 8; j++) acc[i][j] += a[i] * b[j];
        }
        __syncthreads();
    }

#pragma unroll
    for (int i = 0; i < 8; i++) {
        int row = row0 + ty * 8 + i;
        if (row < NN) {
            float o[8];
#pragma unroll
            for (int j = 0; j < 8; j++) {
                float v = acc[i][j] + bj[j];
                o[j] = do_relu ? fmaxf(v, 0.f) : v;
            }
            *(float4*)&out[(size_t)row * 128 + tx * 8]     = make_float4(o[0], o[1], o[2], o[3]);
            *(float4*)&out[(size_t)row * 128 + tx * 8 + 4] = make_float4(o[4], o[5], o[6], o[7]);
        }
    }
}

// ================= decoder: fp16 split-3 wmma (verified skeleton, new dtype) =================
// smem bytes: Ah@0 (34816) Al@34816 (34816)
//             B1@69632: B1h(34816) B1l@104448(34816)  [Sg fp32 128x132=67584 aliases B1 after GEMM1]
//             B2@139264: B2h(17408) B2l@156672(17408)
#define DC_AH  0
#define DC_AL  34816
#define DC_B1  69632
#define DC_B2  139264
#define DC_SMEM 174080

__global__ void __launch_bounds__(256, 1)
k_decoder(const int* __restrict__ pairs,
          const float* __restrict__ Wm1, const float* __restrict__ bm1,
          const float* __restrict__ Wm2, const float* __restrict__ bm2,
          const float* __restrict__ wm3, const float* __restrict__ bm3,
          float* __restrict__ out) {
    extern __shared__ char smc[];
    __half* Ah  = (__half*)(smc + DC_AH);
    __half* Al  = (__half*)(smc + DC_AL);
    __half* B1h = (__half*)(smc + DC_B1);
    __half* B1l = (__half*)(smc + DC_B1 + 34816);
    __half* B2h = (__half*)(smc + DC_B2);
    __half* B2l = (__half*)(smc + DC_B2 + 17408);
    float*  Sg  = (float*)(smc + DC_B1);     // fp32 staging over B1 after GEMM1
    int tid = threadIdx.x, wid = tid >> 5;
    int p0 = blockIdx.x * 128;
    int m0 = wid * 16;

    // stage B1 = Wm1 [128][128] split
    for (int idx = tid * 4; idx < 128 * 128; idx += 1024) {
        int j = idx >> 7, k = idx & 127;
        float4 v = *(const float4*)&Wm1[j * 128 + k];
        uint2 hq, lq;
        split4h(v, hq, lq);
        *(uint2*)&B1h[j * LH + k] = hq;
        *(uint2*)&B1l[j * LH + k] = lq;
    }
    // stage B2 = Wm2 [64][128] split
    for (int idx = tid * 4; idx < 64 * 128; idx += 1024) {
        int j = idx >> 7, k = idx & 127;
        float4 v = *(const float4*)&Wm2[j * 128 + k];
        uint2 hq, lq;
        split4h(v, hq, lq);
        *(uint2*)&B2h[j * LH + k] = hq;
        *(uint2*)&B2l[j * LH + k] = lq;
    }
    // hp = z[i0]*z[i1] -> split-fp16 A (K=128)
    {
        int p = tid >> 1;
        int d0 = (tid & 1) * 64;
        int pg = p0 + p;
        if (pg >= NP) pg = 0;
        int i0 = pairs[(size_t)pg * 2 + 0];
        int i1 = pairs[(size_t)pg * 2 + 1];
        const float* z0 = &g_z[(size_t)i0 * 128 + d0];
        const float* z1 = &g_z[(size_t)i1 * 128 + d0];
#pragma unroll
        for (int t = 0; t < 16; t++) {
            float4 a = *(const float4*)&z0[t * 4];
            float4 b = *(const float4*)&z1[t * 4];
            float4 v = make_float4(a.x * b.x, a.y * b.y, a.z * b.z, a.w * b.w);
            uint2 hq, lq;
            split4h(v, hq, lq);
            *(uint2*)&Ah[p * LH + d0 + t * 4] = hq;
            *(uint2*)&Al[p * LH + d0 + t * 4] = lq;
        }
    }
    __syncthreads();

    // GEMM1: t1 = hp @ Wm1^T  (128x128, K=128, fp16 m16n16k16 x 3 terms)
    wmma::fragment<wmma::accumulator, 16, 16, 16, float> acc1[8];
#pragma unroll
    for (int jt = 0; jt < 8; jt++) wmma::fill_fragment(acc1[jt], 0.f);
    for (int kk = 0; kk < 128; kk += 16) {
        wmma::fragment<wmma::matrix_a, 16, 16, 16, __half, wmma::row_major> ah, al;
        wmma::load_matrix_sync(ah, Ah + m0 * LH + kk, LH);
        wmma::load_matrix_sync(al, Al + m0 * LH + kk, LH);
#pragma unroll
        for (int jt = 0; jt < 8; jt++) {
            wmma::fragment<wmma::matrix_b, 16, 16, 16, __half, wmma::col_major> bh, bl;
            wmma::load_matrix_sync(bh, B1h + jt * 16 * LH + kk, LH);
            wmma::load_matrix_sync(bl, B1l + jt * 16 * LH + kk, LH);
            wmma::mma_sync(acc1[jt], ah, bh, acc1[jt]);
            wmma::mma_sync(acc1[jt], ah, bl, acc1[jt]);
            wmma::mma_sync(acc1[jt], al, bh, acc1[jt]);
        }
    }
    __syncthreads();   // B1 reads done -> Sg may overwrite

#pragma unroll
    for (int jt = 0; jt < 8; jt++)
        wmma::store_matrix_sync(Sg + m0 * LF + jt * 16, acc1[jt], LF, wmma::mem_row_major);
    __syncthreads();

    // t1 = relu(Sg + bm1) -> re-split into A
    for (int idx = tid * 4; idx < 128 * 128; idx += 1024) {
        int r = idx >> 7, k = idx & 127;
        float4 b = *(const float4*)&bm1[k];
        float4 s = *(float4*)&Sg[r * LF + k];
        float4 v = make_float4(fmaxf(s.x + b.x, 0.f), fmaxf(s.y + b.y, 0.f),
                               fmaxf(s.z + b.z, 0.f), fmaxf(s.w + b.w, 0.f));
        uint2 hq, lq;
        split4h(v, hq, lq);
        *(uint2*)&Ah[r * LH + k] = hq;
        *(uint2*)&Al[r * LH + k] = lq;
    }
    __syncthreads();

    // GEMM2: t2 = t1 @ Wm2^T  (128x64, K=128)
    wmma::fragment<wmma::accumulator, 16, 16, 16, float> acc2[4];
#pragma unroll
    for (int jt = 0; jt < 4; jt++) wmma::fill_fragment(acc2[jt], 0.f);
    for (int kk = 0; kk < 128; kk += 16) {
        wmma::fragment<wmma::matrix_a, 16, 16, 16, __half, wmma::row_major> ah, al;
        wmma::load_matrix_sync(ah, Ah + m0 * LH + kk, LH);
        wmma::load_matrix_sync(al, Al + m0 * LH + kk, LH);
#pragma unroll
        for (int jt = 0; jt < 4; jt++) {
            wmma::fragment<wmma::matrix_b, 16, 16, 16, __half, wmma::col_major> bh, bl;
            wmma::load_matrix_sync(bh, B2h + jt * 16 * LH + kk, LH);
            wmma::load_matrix_sync(bl, B2l + jt * 16 * LH + kk, LH);
            wmma::mma_sync(acc2[jt], ah, bh, acc2[jt]);
            wmma::mma_sync(acc2[jt], ah, bl, acc2[jt]);
            wmma::mma_sync(acc2[jt], al, bh, acc2[jt]);
        }
    }
    __syncthreads();   // Sg (t1 staging) reads done in resplit; safe to reuse for final staging
#pragma unroll
    for (int jt = 0; jt < 4; jt++)
        wmma::store_matrix_sync(Sg + m0 * LT + jt * 16, acc2[jt], LT, wmma::mem_row_major);
    __syncthreads();

    // out[p] = sum_j relu(t2[p][j]+bm2[j])*wm3[j] + bm3
    if (tid < 128) {
        int p = p0 + tid;
        float acc = bm3[0];
#pragma unroll 16
        for (int j = 0; j < 64; j++)
            acc += fmaxf(Sg[tid * LT + j] + bm2[j], 0.f) * wm3[j];
        if (p < NP) out[p] = acc;
    }
}

// ================= launch =================
extern "C" void kernel_launch(void* const* d_in, const int* in_sizes, int n_in,
                              void* d_out, int out_size) {
    const float* x     = (const float*)d_in[0];
    const int*   ei    = (const int*)d_in[1];
    const int*   pairs = (const int*)d_in[2];
    const float* W1l = (const float*)d_in[3];
    const float* b1l = (const float*)d_in[4];
    const float* W1r = (const float*)d_in[5];
    const float* W2l = (const float*)d_in[6];
    const float* b2l = (const float*)d_in[7];
    const float* W2r = (const float*)d_in[8];
    const float* Wm1 = (const float*)d_in[9];
    const float* bm1 = (const float*)d_in[10];
    const float* Wm2 = (const float*)d_in[11];
    const float* bm2 = (const float*)d_in[12];
    const float* Wm3 = (const float*)d_in[13];
    const float* bm3 = (const float*)d_in[14];
    float* out = (float*)d_out;
    (void)in_sizes; (void)n_in; (void)out_size;

    size_t smem_layer = (size_t)(256 + 32) * BP * sizeof(float);   // 152064
    cudaFuncSetAttribute(k_gemm_layer, cudaFuncAttributeMaxDynamicSharedMemorySize, (int)smem_layer);
    cudaFuncSetAttribute(k_decoder,    cudaFuncAttributeMaxDynamicSharedMemorySize, DC_SMEM);

    // CSR build
    k_zero<<<(NN + 255) / 256, 256>>>();
    k_count<<<(NE + 255) / 256, 256>>>(ei);
    k_scan<<<1, 1024>>>();
    k_scatter<<<(NE + 255) / 256, 256>>>(ei);
    k_wt<<<(256 * 128 + 255) / 256, 256>>>(W1l, W1r, W2l, W2r);

    // layer 1
    k_aggr<<<(NN * 32 + 255) / 256, 256>>>(x, 1);
    k_gemm_layer<<<(NN + 127) / 128, 256, smem_layer>>>(x, b1l, 1);
    // layer 2
    k_aggr<<<(NN * 32 + 255) / 256, 256>>>(x, 2);
    k_gemm_layer<<<(NN + 127) / 128, 256, smem_layer>>>(g_h, b2l, 2);
    // decoder (fp16 split-3 wmma)
    k_decoder<<<(NP + 127) / 128, 256, DC_SMEM>>>(pairs, Wm1, bm1, Wm2, bm2, Wm3, bm3, out);
}

// round 14
// speedup vs baseline: 1.9314x; 1.2423x over previous
#include <cuda_runtime.h>
#include <cuda_fp16.h>
#include <mma.h>
#include <cstdint>

using namespace nvcuda;

#define NN 100000
#define NE 1600000
#define NP 500000
#define D  128
#define LH  136   // half pitch, K=128 tiles (272B rows; LDSM conflict-free)
#define LB2 264   // half pitch, K=256 layer-B tiles (528B rows; conflict-free)
#define LF  132   // float pitch, staging
#define LT  68    // float pitch, final staging

// ---------------- fp16 split helpers ----------------
__device__ __forceinline__ void split1h(float v, __half& h, __half& l) {
    h = __float2half_rn(v);
    l = __float2half_rn(v - __half2float(h));
}
__device__ __forceinline__ void split4h(float4 v, uint2& hq, uint2& lq) {
    __half h0, h1, h2, h3, l0, l1, l2, l3;
    split1h(v.x, h0, l0); split1h(v.y, h1, l1);
    split1h(v.z, h2, l2); split1h(v.w, h3, l3);
    hq.x = (uint32_t)__half_as_ushort(h0) | ((uint32_t)__half_as_ushort(h1) << 16);
    hq.y = (uint32_t)__half_as_ushort(h2) | ((uint32_t)__half_as_ushort(h3) << 16);
    lq.x = (uint32_t)__half_as_ushort(l0) | ((uint32_t)__half_as_ushort(l1) << 16);
    lq.y = (uint32_t)__half_as_ushort(l2) | ((uint32_t)__half_as_ushort(l3) << 16);
}

// ---------------- scratch ----------------
__device__ int   g_cnt[NN];
__device__ int   g_rowptr[NN + 1];
__device__ int   g_pos[NN];
__device__ float g_inv[NN];
__device__ int   g_srcs[NE];
__device__ float g_aggr[(size_t)NN * D];
__device__ float g_h[(size_t)NN * D];
__device__ float g_z[(size_t)NN * D];
// pre-split weights (hi/lo fp16), [j][k] row-major
__device__ __half g_w1h[128 * 256], g_w1l[128 * 256];   // layer1 [j][k<128:Wl | k>=128:Wr]
__device__ __half g_w2h[128 * 256], g_w2l[128 * 256];   // layer2
__device__ __half g_wm1h[128 * 128], g_wm1l[128 * 128]; // Wm1
__device__ __half g_wm2h[64 * 128],  g_wm2l[64 * 128];  // Wm2

// ---------------- CSR build ----------------
__global__ void k_zero() {
    int i = blockIdx.x * blockDim.x + threadIdx.x;
    if (i < NN) g_cnt[i] = 0;
}
__global__ void k_count(const int* __restrict__ ei) {
    int i = blockIdx.x * blockDim.x + threadIdx.x;
    if (i < NE) atomicAdd(&g_cnt[ei[NE + i]], 1);
}
__global__ void k_scan() {
    __shared__ int s[1024];
    int tid = threadIdx.x;
    int base = 0;
    for (int start = 0; start < NN; start += 1024) {
        int i = start + tid;
        int v = (i < NN) ? g_cnt[i] : 0;
        s[tid] = v;
        __syncthreads();
        for (int off = 1; off < 1024; off <<= 1) {
            int t = (tid >= off) ? s[tid - off] : 0;
            __syncthreads();
            s[tid] += t;
            __syncthreads();
        }
        int excl = base + s[tid] - v;
        if (i < NN) {
            g_rowptr[i] = excl;
            g_pos[i]    = excl;
            g_inv[i]    = 1.0f / (float)(v > 0 ? v : 1);
        }
        base += s[1023];
        __syncthreads();
    }
    if (tid == 0) g_rowptr[NN] = base;
}
__global__ void k_scatter(const int* __restrict__ ei) {
    int i = blockIdx.x * blockDim.x + threadIdx.x;
    if (i < NE) {
        int dst = ei[NE + i];
        int src = ei[i];
        int p = atomicAdd(&g_pos[dst], 1);
        g_srcs[p] = src;
    }
}

// ---------------- one-time weight split ----------------
__global__ void k_wt(const float* __restrict__ W1l, const float* __restrict__ W1r,
                     const float* __restrict__ W2l, const float* __restrict__ W2r,
                     const float* __restrict__ Wm1, const float* __restrict__ Wm2) {
    int i = blockIdx.x * blockDim.x + threadIdx.x;
    if (i < 128 * 256) {
        int j = i >> 8, k = i & 255;
        float v1 = (k < 128) ? W1l[j * 128 + k] : W1r[j * 128 + (k - 128)];
        float v2 = (k < 128) ? W2l[j * 128 + k] : W2r[j * 128 + (k - 128)];
        split1h(v1, g_w1h[i], g_w1l[i]);
        split1h(v2, g_w2h[i], g_w2l[i]);
    }
    if (i < 128 * 128) split1h(Wm1[i], g_wm1h[i], g_wm1l[i]);
    if (i < 64 * 128)  split1h(Wm2[i], g_wm2h[i], g_wm2l[i]);
}

// ---------------- mean aggregation ----------------
__global__ void k_aggr(const float* __restrict__ x, int layer) {
    const float* __restrict__ feat = (layer == 1) ? x : g_h;
    int warp = (blockIdx.x * blockDim.x + threadIdx.x) >> 5;
    int lane = threadIdx.x & 31;
    if (warp >= NN) return;
    int beg = g_rowptr[warp], end = g_rowptr[warp + 1];
    float4 acc = make_float4(0.f, 0.f, 0.f, 0.f);
    for (int e = beg; e < end; e++) {
        int s = g_srcs[e];
        float4 v = *(const float4*)&feat[(size_t)s * D + lane * 4];
        acc.x += v.x; acc.y += v.y; acc.z += v.z; acc.w += v.w;
    }
    float inv = g_inv[warp];
    acc.x *= inv; acc.y *= inv; acc.z *= inv; acc.w *= inv;
    *(float4*)&g_aggr[(size_t)warp * D + lane * 4] = acc;
}

// ================= layer GEMM: fp16 split-3 wmma (decoder-verified skeleton) =================
// out[row][j] = relu?( sum_{k<256} cat(aggr,self)[row][k] * Wcat[j][k] + b[j] )
// smem: Bh@0 [128][264]h 67584, Bl@67584, Ah@135168 [128][136]h 34816, Al@169984 ; 204800 B
// Sg (fp32 [128][132] = 67584) aliases Ah/Al after compute.
#define LY_BH 0
#define LY_BL 67584
#define LY_A  135168
#define LY_SMEM 204800

__global__ void __launch_bounds__(256, 1)
k_gemm_layer(const float* __restrict__ x, const float* __restrict__ bias, int layer) {
    extern __shared__ char smc[];
    __half* Bh = (__half*)(smc + LY_BH);
    __half* Bl = (__half*)(smc + LY_BL);
    __half* Ah = (__half*)(smc + LY_A);
    __half* Al = (__half*)(smc + LY_A + 34816);
    float*  Sg = (float*)(smc + LY_A);

    const float* __restrict__ self = (layer == 1) ? x : g_h;
    const __half* __restrict__ wbh = (layer == 1) ? g_w1h : g_w2h;
    const __half* __restrict__ wbl = (layer == 1) ? g_w1l : g_w2l;
    float* __restrict__ out        = (layer == 1) ? g_h : g_z;
    const int do_relu = (layer == 1);

    int tid = threadIdx.x, wid = tid >> 5;
    int row0 = blockIdx.x * 128;
    int m0 = wid * 16;

    // stage B (pre-split copy): [j 0..127][k 0..255]
    for (int idx = tid * 8; idx < 128 * 256; idx += 2048) {
        int j = idx >> 8, k = idx & 255;
        *(uint4*)&Bh[j * LB2 + k] = *(const uint4*)&wbh[j * 256 + k];
        *(uint4*)&Bl[j * LB2 + k] = *(const uint4*)&wbl[j * 256 + k];
    }

    wmma::fragment<wmma::accumulator, 16, 16, 16, float> acc[8];
#pragma unroll
    for (int jt = 0; jt < 8; jt++) wmma::fill_fragment(acc[jt], 0.f);

    for (int ph = 0; ph < 2; ph++) {
        const float* __restrict__ A = (ph == 0) ? g_aggr : self;
        // stage A phase: rows row0..+127, local k 0..127, split to fp16 hi/lo
        for (int idx = tid * 4; idx < 128 * 128; idx += 1024) {
            int r = idx >> 7, k = idx & 127;
            int row = row0 + r;
            float4 v = make_float4(0.f, 0.f, 0.f, 0.f);
            if (row < NN) v = *(const float4*)&A[(size_t)row * 128 + k];
            uint2 hq, lq;
            split4h(v, hq, lq);
            *(uint2*)&Ah[r * LH + k] = hq;
            *(uint2*)&Al[r * LH + k] = lq;
        }
        __syncthreads();
        for (int kk = 0; kk < 128; kk += 16) {
            wmma::fragment<wmma::matrix_a, 16, 16, 16, __half, wmma::row_major> ah, al;
            wmma::load_matrix_sync(ah, Ah + m0 * LH + kk, LH);
            wmma::load_matrix_sync(al, Al + m0 * LH + kk, LH);
            int kg = ph * 128 + kk;
#pragma unroll
            for (int jt = 0; jt < 8; jt++) {
                wmma::fragment<wmma::matrix_b, 16, 16, 16, __half, wmma::col_major> bh, bl;
                wmma::load_matrix_sync(bh, Bh + jt * 16 * LB2 + kg, LB2);
                wmma::load_matrix_sync(bl, Bl + jt * 16 * LB2 + kg, LB2);
                wmma::mma_sync(acc[jt], ah, bh, acc[jt]);
                wmma::mma_sync(acc[jt], ah, bl, acc[jt]);
                wmma::mma_sync(acc[jt], al, bh, acc[jt]);
            }
        }
        __syncthreads();
    }

    // epilogue: stage fp32, bias+relu, store
#pragma unroll
    for (int jt = 0; jt < 8; jt++)
        wmma::store_matrix_sync(Sg + m0 * LF + jt * 16, acc[jt], LF, wmma::mem_row_major);
    __syncthreads();
    for (int idx = tid * 4; idx < 128 * 128; idx += 1024) {
        int r = idx >> 7, j = idx & 127;
        int row = row0 + r;
        if (row < NN) {
            float4 b = *(const float4*)&bias[j];
            float4 s = *(float4*)&Sg[r * LF + j];
            float4 o;
            o.x = s.x + b.x; o.y = s.y + b.y; o.z = s.z + b.z; o.w = s.w + b.w;
            if (do_relu) {
                o.x = fmaxf(o.x, 0.f); o.y = fmaxf(o.y, 0.f);
                o.z = fmaxf(o.z, 0.f); o.w = fmaxf(o.w, 0.f);
            }
            *(float4*)&out[(size_t)row * 128 + j] = o;
        }
    }
}

// ================= decoder: fp16 split-3 wmma (verified; weights pre-split) =================
#define DC_AH  0
#define DC_AL  34816
#define DC_B1  69632
#define DC_B2  139264
#define DC_SMEM 174080

__global__ void __launch_bounds__(256, 1)
k_decoder(const int* __restrict__ pairs,
          const float* __restrict__ bm1, const float* __restrict__ bm2,
          const float* __restrict__ wm3, const float* __restrict__ bm3,
          float* __restrict__ out) {
    extern __shared__ char smc[];
    __half* Ah  = (__half*)(smc + DC_AH);
    __half* Al  = (__half*)(smc + DC_AL);
    __half* B1h = (__half*)(smc + DC_B1);
    __half* B1l = (__half*)(smc + DC_B1 + 34816);
    __half* B2h = (__half*)(smc + DC_B2);
    __half* B2l = (__half*)(smc + DC_B2 + 17408);
    float*  Sg  = (float*)(smc + DC_B1);     // fp32 staging over B1 after GEMM1
    int tid = threadIdx.x, wid = tid >> 5;
    int p0 = blockIdx.x * 128;
    int m0 = wid * 16;

    // stage B1 (pre-split copy) [128][128]
    for (int idx = tid * 8; idx < 128 * 128; idx += 2048) {
        int j = idx >> 7, k = idx & 127;
        *(uint4*)&B1h[j * LH + k] = *(const uint4*)&g_wm1h[j * 128 + k];
        *(uint4*)&B1l[j * LH + k] = *(const uint4*)&g_wm1l[j * 128 + k];
    }
    // stage B2 (pre-split copy) [64][128]
    for (int idx = tid * 8; idx < 64 * 128; idx += 2048) {
        int j = idx >> 7, k = idx & 127;
        *(uint4*)&B2h[j * LH + k] = *(const uint4*)&g_wm2h[j * 128 + k];
        *(uint4*)&B2l[j * LH + k] = *(const uint4*)&g_wm2l[j * 128 + k];
    }
    // hp = z[i0]*z[i1] -> split-fp16 A (K=128)
    {
        int p = tid >> 1;
        int d0 = (tid & 1) * 64;
        int pg = p0 + p;
        if (pg >= NP) pg = 0;
        int i0 = pairs[(size_t)pg * 2 + 0];
        int i1 = pairs[(size_t)pg * 2 + 1];
        const float* z0 = &g_z[(size_t)i0 * 128 + d0];
        const float* z1 = &g_z[(size_t)i1 * 128 + d0];
#pragma unroll
        for (int t = 0; t < 16; t++) {
            float4 a = *(const float4*)&z0[t * 4];
            float4 b = *(const float4*)&z1[t * 4];
            float4 v = make_float4(a.x * b.x, a.y * b.y, a.z * b.z, a.w * b.w);
            uint2 hq, lq;
            split4h(v, hq, lq);
            *(uint2*)&Ah[p * LH + d0 + t * 4] = hq;
            *(uint2*)&Al[p * LH + d0 + t * 4] = lq;
        }
    }
    __syncthreads();

    // GEMM1: t1 = hp @ Wm1^T  (128x128, K=128)
    wmma::fragment<wmma::accumulator, 16, 16, 16, float> acc1[8];
#pragma unroll
    for (int jt = 0; jt < 8; jt++) wmma::fill_fragment(acc1[jt], 0.f);
    for (int kk = 0; kk < 128; kk += 16) {
        wmma::fragment<wmma::matrix_a, 16, 16, 16, __half, wmma::row_major> ah, al;
        wmma::load_matrix_sync(ah, Ah + m0 * LH + kk, LH);
        wmma::load_matrix_sync(al, Al + m0 * LH + kk, LH);
#pragma unroll
        for (int jt = 0; jt < 8; jt++) {
            wmma::fragment<wmma::matrix_b, 16, 16, 16, __half, wmma::col_major> bh, bl;
            wmma::load_matrix_sync(bh, B1h + jt * 16 * LH + kk, LH);
            wmma::load_matrix_sync(bl, B1l + jt * 16 * LH + kk, LH);
            wmma::mma_sync(acc1[jt], ah, bh, acc1[jt]);
            wmma::mma_sync(acc1[jt], ah, bl, acc1[jt]);
            wmma::mma_sync(acc1[jt], al, bh, acc1[jt]);
        }
    }
    __syncthreads();   // B1 reads done -> Sg may overwrite

#pragma unroll
    for (int jt = 0; jt < 8; jt++)
        wmma::store_matrix_sync(Sg + m0 * LF + jt * 16, acc1[jt], LF, wmma::mem_row_major);
    __syncthreads();

    // t1 = relu(Sg + bm1) -> re-split into A
    for (int idx = tid * 4; idx < 128 * 128; idx += 1024) {
        int r = idx >> 7, k = idx & 127;
        float4 b = *(const float4*)&bm1[k];
        float4 s = *(float4*)&Sg[r * LF + k];
        float4 v = make_float4(fmaxf(s.x + b.x, 0.f), fmaxf(s.y + b.y, 0.f),
                               fmaxf(s.z + b.z, 0.f), fmaxf(s.w + b.w, 0.f));
        uint2 hq, lq;
        split4h(v, hq, lq);
        *(uint2*)&Ah[r * LH + k] = hq;
        *(uint2*)&Al[r * LH + k] = lq;
    }
    __syncthreads();

    // GEMM2: t2 = t1 @ Wm2^T  (128x64, K=128)
    wmma::fragment<wmma::accumulator, 16, 16, 16, float> acc2[4];
#pragma unroll
    for (int jt = 0; jt < 4; jt++) wmma::fill_fragment(acc2[jt], 0.f);
    for (int kk = 0; kk < 128; kk += 16) {
        wmma::fragment<wmma::matrix_a, 16, 16, 16, __half, wmma::row_major> ah, al;
        wmma::load_matrix_sync(ah, Ah + m0 * LH + kk, LH);
        wmma::load_matrix_sync(al, Al + m0 * LH + kk, LH);
#pragma unroll
        for (int jt = 0; jt < 4; jt++) {
            wmma::fragment<wmma::matrix_b, 16, 16, 16, __half, wmma::col_major> bh, bl;
            wmma::load_matrix_sync(bh, B2h + jt * 16 * LH + kk, LH);
            wmma::load_matrix_sync(bl, B2l + jt * 16 * LH + kk, LH);
            wmma::mma_sync(acc2[jt], ah, bh, acc2[jt]);
            wmma::mma_sync(acc2[jt], ah, bl, acc2[jt]);
            wmma::mma_sync(acc2[jt], al, bh, acc2[jt]);
        }
    }
    __syncthreads();
#pragma unroll
    for (int jt = 0; jt < 4; jt++)
        wmma::store_matrix_sync(Sg + m0 * LT + jt * 16, acc2[jt], LT, wmma::mem_row_major);
    __syncthreads();

    // out[p] = sum_j relu(t2[p][j]+bm2[j])*wm3[j] + bm3
    if (tid < 128) {
        int p = p0 + tid;
        float acc = bm3[0];
#pragma unroll 16
        for (int j = 0; j < 64; j++)
            acc += fmaxf(Sg[tid * LT + j] + bm2[j], 0.f) * wm3[j];
        if (p < NP) out[p] = acc;
    }
}

// ================= launch =================
extern "C" void kernel_launch(void* const* d_in, const int* in_sizes, int n_in,
                              void* d_out, int out_size) {
    const float* x     = (const float*)d_in[0];
    const int*   ei    = (const int*)d_in[1];
    const int*   pairs = (const int*)d_in[2];
    const float* W1l = (const float*)d_in[3];
    const float* b1l = (const float*)d_in[4];
    const float* W1r = (const float*)d_in[5];
    const float* W2l = (const float*)d_in[6];
    const float* b2l = (const float*)d_in[7];
    const float* W2r = (const float*)d_in[8];
    const float* Wm1 = (const float*)d_in[9];
    const float* bm1 = (const float*)d_in[10];
    const float* Wm2 = (const float*)d_in[11];
    const float* bm2 = (const float*)d_in[12];
    const float* Wm3 = (const float*)d_in[13];
    const float* bm3 = (const float*)d_in[14];
    float* out = (float*)d_out;
    (void)in_sizes; (void)n_in; (void)out_size;

    cudaFuncSetAttribute(k_gemm_layer, cudaFuncAttributeMaxDynamicSharedMemorySize, LY_SMEM);
    cudaFuncSetAttribute(k_decoder,    cudaFuncAttributeMaxDynamicSharedMemorySize, DC_SMEM);

    // CSR build + one-time weight split
    k_zero<<<(NN + 255) / 256, 256>>>();
    k_count<<<(NE + 255) / 256, 256>>>(ei);
    k_scan<<<1, 1024>>>();
    k_scatter<<<(NE + 255) / 256, 256>>>(ei);
    k_wt<<<(128 * 256 + 255) / 256, 256>>>(W1l, W1r, W2l, W2r, Wm1, Wm2);

    // layer 1: h = relu(aggr@W1l^T + b1l + x@W1r^T)
    k_aggr<<<(NN * 32 + 255) / 256, 256>>>(x, 1);
    k_gemm_layer<<<(NN + 127) / 128, 256, LY_SMEM>>>(x, b1l, 1);
    // layer 2: z = aggr(h)@W2l^T + b2l + h@W2r^T
    k_aggr<<<(NN * 32 + 255) / 256, 256>>>(x, 2);
    k_gemm_layer<<<(NN + 127) / 128, 256, LY_SMEM>>>(x, b2l, 2);
    // decoder
    k_decoder<<<(NP + 127) / 128, 256, DC_SMEM>>>(pairs, bm1, bm2, Wm3, bm3, out);
}

// round 15
// speedup vs baseline: 1.9825x; 1.0265x over previous
#include <cuda_runtime.h>
#include <cuda_fp16.h>
#include <mma.h>
#include <cstdint>

using namespace nvcuda;

#define NN 100000
#define NE 1600000
#define NP 500000
#define D  128
#define LH  136   // half pitch, K=128 tiles (272B rows; LDSM conflict-free)
#define LB2 264   // half pitch, K=256 layer-B tiles
#define LF  132   // float pitch, staging
#define LT  68    // float pitch, final staging
#define SCAN_NB 98  // ceil(NN/1024)

// ---------------- fp16 split helpers ----------------
__device__ __forceinline__ void split1h(float v, __half& h, __half& l) {
    h = __float2half_rn(v);
    l = __float2half_rn(v - __half2float(h));
}
__device__ __forceinline__ void split4h(float4 v, uint2& hq, uint2& lq) {
    __half h0, h1, h2, h3, l0, l1, l2, l3;
    split1h(v.x, h0, l0); split1h(v.y, h1, l1);
    split1h(v.z, h2, l2); split1h(v.w, h3, l3);
    hq.x = (uint32_t)__half_as_ushort(h0) | ((uint32_t)__half_as_ushort(h1) << 16);
    hq.y = (uint32_t)__half_as_ushort(h2) | ((uint32_t)__half_as_ushort(h3) << 16);
    lq.x = (uint32_t)__half_as_ushort(l0) | ((uint32_t)__half_as_ushort(l1) << 16);
    lq.y = (uint32_t)__half_as_ushort(l2) | ((uint32_t)__half_as_ushort(l3) << 16);
}

// ---------------- scratch ----------------
__device__ int   g_cnt[NN];
__device__ int   g_rowptr[NN + 1];
__device__ int   g_pos[NN];
__device__ float g_inv[NN];
__device__ int   g_srcs[NE];
__device__ float g_aggr[(size_t)NN * D];
__device__ float g_h[(size_t)NN * D];
__device__ float g_z[(size_t)NN * D];
__device__ volatile int g_blk_val[SCAN_NB];
__device__ volatile int g_blk_flag[SCAN_NB];
// pre-split weights (hi/lo fp16), [j][k] row-major
__device__ __half g_w1h[128 * 256], g_w1l[128 * 256];
__device__ __half g_w2h[128 * 256], g_w2l[128 * 256];
__device__ __half g_wm1h[128 * 128], g_wm1l[128 * 128];
__device__ __half g_wm2h[64 * 128],  g_wm2l[64 * 128];

// ---------------- merged zero + weight split + flag clear ----------------
__global__ void k_zerowt(const float* __restrict__ W1l, const float* __restrict__ W1r,
                         const float* __restrict__ W2l, const float* __restrict__ W2r,
                         const float* __restrict__ Wm1, const float* __restrict__ Wm2) {
    int i = blockIdx.x * blockDim.x + threadIdx.x;
    if (i < NN) g_cnt[i] = 0;
    if (i < SCAN_NB) g_blk_flag[i] = 0;
    if (i < 128 * 256) {
        int j = i >> 8, k = i & 255;
        float v1 = (k < 128) ? W1l[j * 128 + k] : W1r[j * 128 + (k - 128)];
        float v2 = (k < 128) ? W2l[j * 128 + k] : W2r[j * 128 + (k - 128)];
        split1h(v1, g_w1h[i], g_w1l[i]);
        split1h(v2, g_w2h[i], g_w2l[i]);
    }
    if (i < 128 * 128) split1h(Wm1[i], g_wm1h[i], g_wm1l[i]);
    if (i < 64 * 128)  split1h(Wm2[i], g_wm2h[i], g_wm2l[i]);
}

__global__ void k_count(const int* __restrict__ ei) {
    int i = blockIdx.x * blockDim.x + threadIdx.x;
    if (i < NE) atomicAdd(&g_cnt[ei[NE + i]], 1);
}

// ---------------- multi-block scan with chained lookback ----------------
__global__ void __launch_bounds__(1024, 1) k_scan() {
    __shared__ int sw[32];
    __shared__ int s_pfx;
    int b = blockIdx.x, tid = threadIdx.x;
    int i = b * 1024 + tid;
    int lane = tid & 31, wid = tid >> 5;
    int v = (i < NN) ? g_cnt[i] : 0;
    // warp inclusive scan
    int x = v;
#pragma unroll
    for (int o = 1; o < 32; o <<= 1) {
        int t = __shfl_up_sync(0xffffffffu, x, o);
        if (lane >= o) x += t;
    }
    if (lane == 31) sw[wid] = x;
    __syncthreads();
    if (wid == 0) {
        int y = sw[lane];
#pragma unroll
        for (int o = 1; o < 32; o <<= 1) {
            int t = __shfl_up_sync(0xffffffffu, y, o);
            if (lane >= o) y += t;
        }
        sw[lane] = y;
    }
    __syncthreads();
    int incl = x + (wid > 0 ? sw[wid - 1] : 0);
    int total = sw[31];
    if (tid == 0) {
        int pfx = 0;
        if (b > 0) {
            while (g_blk_flag[b - 1] == 0) { }
            __threadfence();
            pfx = g_blk_val[b - 1];
        }
        s_pfx = pfx;
        g_blk_val[b] = pfx + total;
        __threadfence();
        g_blk_flag[b] = 1;
    }
    __syncthreads();
    int pfx = s_pfx;
    int excl = pfx + incl - v;
    if (i < NN) {
        g_rowptr[i] = excl;
        g_pos[i]    = excl;
        g_inv[i]    = 1.0f / (float)(v > 0 ? v : 1);
        if (i == NN - 1) g_rowptr[NN] = excl + v;
    }
}

__global__ void k_scatter(const int* __restrict__ ei) {
    int i = blockIdx.x * blockDim.x + threadIdx.x;
    if (i < NE) {
        int dst = ei[NE + i];
        int src = ei[i];
        int p = atomicAdd(&g_pos[dst], 1);
        g_srcs[p] = src;
    }
}

// ---------------- mean aggregation (unroll x4 for MLP) ----------------
__global__ void k_aggr(const float* __restrict__ x, int layer) {
    const float* __restrict__ feat = (layer == 1) ? x : g_h;
    int warp = (blockIdx.x * blockDim.x + threadIdx.x) >> 5;
    int lane = threadIdx.x & 31;
    if (warp >= NN) return;
    int beg = g_rowptr[warp], end = g_rowptr[warp + 1];
    float4 acc = make_float4(0.f, 0.f, 0.f, 0.f);
    int e = beg;
    for (; e + 4 <= end; e += 4) {
        int s0 = g_srcs[e], s1 = g_srcs[e + 1], s2 = g_srcs[e + 2], s3 = g_srcs[e + 3];
        float4 v0 = *(const float4*)&feat[(size_t)s0 * D + lane * 4];
        float4 v1 = *(const float4*)&feat[(size_t)s1 * D + lane * 4];
        float4 v2 = *(const float4*)&feat[(size_t)s2 * D + lane * 4];
        float4 v3 = *(const float4*)&feat[(size_t)s3 * D + lane * 4];
        acc.x += v0.x; acc.y += v0.y; acc.z += v0.z; acc.w += v0.w;
        acc.x += v1.x; acc.y += v1.y; acc.z += v1.z; acc.w += v1.w;
        acc.x += v2.x; acc.y += v2.y; acc.z += v2.z; acc.w += v2.w;
        acc.x += v3.x; acc.y += v3.y; acc.z += v3.z; acc.w += v3.w;
    }
    for (; e < end; e++) {
        int s = g_srcs[e];
        float4 v = *(const float4*)&feat[(size_t)s * D + lane * 4];
        acc.x += v.x; acc.y += v.y; acc.z += v.z; acc.w += v.w;
    }
    float inv = g_inv[warp];
    acc.x *= inv; acc.y *= inv; acc.z *= inv; acc.w *= inv;
    *(float4*)&g_aggr[(size_t)warp * D + lane * 4] = acc;
}

// ================= layer GEMM: fp16 split-3 wmma (UNCHANGED from R14) =================
#define LY_BH 0
#define LY_BL 67584
#define LY_A  135168
#define LY_SMEM 204800

__global__ void __launch_bounds__(256, 1)
k_gemm_layer(const float* __restrict__ x, const float* __restrict__ bias, int layer) {
    extern __shared__ char smc[];
    __half* Bh = (__half*)(smc + LY_BH);
    __half* Bl = (__half*)(smc + LY_BL);
    __half* Ah = (__half*)(smc + LY_A);
    __half* Al = (__half*)(smc + LY_A + 34816);
    float*  Sg = (float*)(smc + LY_A);

    const float* __restrict__ self = (layer == 1) ? x : g_h;
    const __half* __restrict__ wbh = (layer == 1) ? g_w1h : g_w2h;
    const __half* __restrict__ wbl = (layer == 1) ? g_w1l : g_w2l;
    float* __restrict__ out        = (layer == 1) ? g_h : g_z;
    const int do_relu = (layer == 1);

    int tid = threadIdx.x, wid = tid >> 5;
    int row0 = blockIdx.x * 128;
    int m0 = wid * 16;

    for (int idx = tid * 8; idx < 128 * 256; idx += 2048) {
        int j = idx >> 8, k = idx & 255;
        *(uint4*)&Bh[j * LB2 + k] = *(const uint4*)&wbh[j * 256 + k];
        *(uint4*)&Bl[j * LB2 + k] = *(const uint4*)&wbl[j * 256 + k];
    }

    wmma::fragment<wmma::accumulator, 16, 16, 16, float> acc[8];
#pragma unroll
    for (int jt = 0; jt < 8; jt++) wmma::fill_fragment(acc[jt], 0.f);

    for (int ph = 0; ph < 2; ph++) {
        const float* __restrict__ A = (ph == 0) ? g_aggr : self;
        for (int idx = tid * 4; idx < 128 * 128; idx += 1024) {
            int r = idx >> 7, k = idx & 127;
            int row = row0 + r;
            float4 v = make_float4(0.f, 0.f, 0.f, 0.f);
            if (row < NN) v = *(const float4*)&A[(size_t)row * 128 + k];
            uint2 hq, lq;
            split4h(v, hq, lq);
            *(uint2*)&Ah[r * LH + k] = hq;
            *(uint2*)&Al[r * LH + k] = lq;
        }
        __syncthreads();
        for (int kk = 0; kk < 128; kk += 16) {
            wmma::fragment<wmma::matrix_a, 16, 16, 16, __half, wmma::row_major> ah, al;
            wmma::load_matrix_sync(ah, Ah + m0 * LH + kk, LH);
            wmma::load_matrix_sync(al, Al + m0 * LH + kk, LH);
            int kg = ph * 128 + kk;
#pragma unroll
            for (int jt = 0; jt < 8; jt++) {
                wmma::fragment<wmma::matrix_b, 16, 16, 16, __half, wmma::col_major> bh, bl;
                wmma::load_matrix_sync(bh, Bh + jt * 16 * LB2 + kg, LB2);
                wmma::load_matrix_sync(bl, Bl + jt * 16 * LB2 + kg, LB2);
                wmma::mma_sync(acc[jt], ah, bh, acc[jt]);
                wmma::mma_sync(acc[jt], ah, bl, acc[jt]);
                wmma::mma_sync(acc[jt], al, bh, acc[jt]);
            }
        }
        __syncthreads();
    }

#pragma unroll
    for (int jt = 0; jt < 8; jt++)
        wmma::store_matrix_sync(Sg + m0 * LF + jt * 16, acc[jt], LF, wmma::mem_row_major);
    __syncthreads();
    for (int idx = tid * 4; idx < 128 * 128; idx += 1024) {
        int r = idx >> 7, j = idx & 127;
        int row = row0 + r;
        if (row < NN) {
            float4 b = *(const float4*)&bias[j];
            float4 s = *(float4*)&Sg[r * LF + j];
            float4 o;
            o.x = s.x + b.x; o.y = s.y + b.y; o.z = s.z + b.z; o.w = s.w + b.w;
            if (do_relu) {
                o.x = fmaxf(o.x, 0.f); o.y = fmaxf(o.y, 0.f);
                o.z = fmaxf(o.z, 0.f); o.w = fmaxf(o.w, 0.f);
            }
            *(float4*)&out[(size_t)row * 128 + j] = o;
        }
    }
}

// ================= decoder: fp16 split-3 wmma (UNCHANGED from R14) =================
#define DC_AH  0
#define DC_AL  34816
#define DC_B1  69632
#define DC_B2  139264
#define DC_SMEM 174080

__global__ void __launch_bounds__(256, 1)
k_decoder(const int* __restrict__ pairs,
          const float* __restrict__ bm1, const float* __restrict__ bm2,
          const float* __restrict__ wm3, const float* __restrict__ bm3,
          float* __restrict__ out) {
    extern __shared__ char smc[];
    __half* Ah  = (__half*)(smc + DC_AH);
    __half* Al  = (__half*)(smc + DC_AL);
    __half* B1h = (__half*)(smc + DC_B1);
    __half* B1l = (__half*)(smc + DC_B1 + 34816);
    __half* B2h = (__half*)(smc + DC_B2);
    __half* B2l = (__half*)(smc + DC_B2 + 17408);
    float*  Sg  = (float*)(smc + DC_B1);
    int tid = threadIdx.x, wid = tid >> 5;
    int p0 = blockIdx.x * 128;
    int m0 = wid * 16;

    for (int idx = tid * 8; idx < 128 * 128; idx += 2048) {
        int j = idx >> 7, k = idx & 127;
        *(uint4*)&B1h[j * LH + k] = *(const uint4*)&g_wm1h[j * 128 + k];
        *(uint4*)&B1l[j * LH + k] = *(const uint4*)&g_wm1l[j * 128 + k];
    }
    for (int idx = tid * 8; idx < 64 * 128; idx += 2048) {
        int j = idx >> 7, k = idx & 127;
        *(uint4*)&B2h[j * LH + k] = *(const uint4*)&g_wm2h[j * 128 + k];
        *(uint4*)&B2l[j * LH + k] = *(const uint4*)&g_wm2l[j * 128 + k];
    }
    {
        int p = tid >> 1;
        int d0 = (tid & 1) * 64;
        int pg = p0 + p;
        if (pg >= NP) pg = 0;
        int i0 = pairs[(size_t)pg * 2 + 0];
        int i1 = pairs[(size_t)pg * 2 + 1];
        const float* z0 = &g_z[(size_t)i0 * 128 + d0];
        const float* z1 = &g_z[(size_t)i1 * 128 + d0];
#pragma unroll
        for (int t = 0; t < 16; t++) {
            float4 a = *(const float4*)&z0[t * 4];
            float4 b = *(const float4*)&z1[t * 4];
            float4 v = make_float4(a.x * b.x, a.y * b.y, a.z * b.z, a.w * b.w);
            uint2 hq, lq;
            split4h(v, hq, lq);
            *(uint2*)&Ah[p * LH + d0 + t * 4] = hq;
            *(uint2*)&Al[p * LH + d0 + t * 4] = lq;
        }
    }
    __syncthreads();

    wmma::fragment<wmma::accumulator, 16, 16, 16, float> acc1[8];
#pragma unroll
    for (int jt = 0; jt < 8; jt++) wmma::fill_fragment(acc1[jt], 0.f);
    for (int kk = 0; kk < 128; kk += 16) {
        wmma::fragment<wmma::matrix_a, 16, 16, 16, __half, wmma::row_major> ah, al;
        wmma::load_matrix_sync(ah, Ah + m0 * LH + kk, LH);
        wmma::load_matrix_sync(al, Al + m0 * LH + kk, LH);
#pragma unroll
        for (int jt = 0; jt < 8; jt++) {
            wmma::fragment<wmma::matrix_b, 16, 16, 16, __half, wmma::col_major> bh, bl;
            wmma::load_matrix_sync(bh, B1h + jt * 16 * LH + kk, LH);
            wmma::load_matrix_sync(bl, B1l + jt * 16 * LH + kk, LH);
            wmma::mma_sync(acc1[jt], ah, bh, acc1[jt]);
            wmma::mma_sync(acc1[jt], ah, bl, acc1[jt]);
            wmma::mma_sync(acc1[jt], al, bh, acc1[jt]);
        }
    }
    __syncthreads();

#pragma unroll
    for (int jt = 0; jt < 8; jt++)
        wmma::store_matrix_sync(Sg + m0 * LF + jt * 16, acc1[jt], LF, wmma::mem_row_major);
    __syncthreads();

    for (int idx = tid * 4; idx < 128 * 128; idx += 1024) {
        int r = idx >> 7, k = idx & 127;
        float4 b = *(const float4*)&bm1[k];
        float4 s = *(float4*)&Sg[r * LF + k];
        float4 v = make_float4(fmaxf(s.x + b.x, 0.f), fmaxf(s.y + b.y, 0.f),
                               fmaxf(s.z + b.z, 0.f), fmaxf(s.w + b.w, 0.f));
        uint2 hq, lq;
        split4h(v, hq, lq);
        *(uint2*)&Ah[r * LH + k] = hq;
        *(uint2*)&Al[r * LH + k] = lq;
    }
    __syncthreads();

    wmma::fragment<wmma::accumulator, 16, 16, 16, float> acc2[4];
#pragma unroll
    for (int jt = 0; jt < 4; jt++) wmma::fill_fragment(acc2[jt], 0.f);
    for (int kk = 0; kk < 128; kk += 16) {
        wmma::fragment<wmma::matrix_a, 16, 16, 16, __half, wmma::row_major> ah, al;
        wmma::load_matrix_sync(ah, Ah + m0 * LH + kk, LH);
        wmma::load_matrix_sync(al, Al + m0 * LH + kk, LH);
#pragma unroll
        for (int jt = 0; jt < 4; jt++) {
            wmma::fragment<wmma::matrix_b, 16, 16, 16, __half, wmma::col_major> bh, bl;
            wmma::load_matrix_sync(bh, B2h + jt * 16 * LH + kk, LH);
            wmma::load_matrix_sync(bl, B2l + jt * 16 * LH + kk, LH);
            wmma::mma_sync(acc2[jt], ah, bh, acc2[jt]);
            wmma::mma_sync(acc2[jt], ah, bl, acc2[jt]);
            wmma::mma_sync(acc2[jt], al, bh, acc2[jt]);
        }
    }
    __syncthreads();
#pragma unroll
    for (int jt = 0; jt < 4; jt++)
        wmma::store_matrix_sync(Sg + m0 * LT + jt * 16, acc2[jt], LT, wmma::mem_row_major);
    __syncthreads();

    if (tid < 128) {
        int p = p0 + tid;
        float acc = bm3[0];
#pragma unroll 16
        for (int j = 0; j < 64; j++)
            acc += fmaxf(Sg[tid * LT + j] + bm2[j], 0.f) * wm3[j];
        if (p < NP) out[p] = acc;
    }
}

// ================= launch =================
extern "C" void kernel_launch(void* const* d_in, const int* in_sizes, int n_in,
                              void* d_out, int out_size) {
    const float* x     = (const float*)d_in[0];
    const int*   ei    = (const int*)d_in[1];
    const int*   pairs = (const int*)d_in[2];
    const float* W1l = (const float*)d_in[3];
    const float* b1l = (const float*)d_in[4];
    const float* W1r = (const float*)d_in[5];
    const float* W2l = (const float*)d_in[6];
    const float* b2l = (const float*)d_in[7];
    const float* W2r = (const float*)d_in[8];
    const float* Wm1 = (const float*)d_in[9];
    const float* bm1 = (const float*)d_in[10];
    const float* Wm2 = (const float*)d_in[11];
    const float* bm2 = (const float*)d_in[12];
    const float* Wm3 = (const float*)d_in[13];
    const float* bm3 = (const float*)d_in[14];
    float* out = (float*)d_out;
    (void)in_sizes; (void)n_in; (void)out_size;

    cudaFuncSetAttribute(k_gemm_layer, cudaFuncAttributeMaxDynamicSharedMemorySize, LY_SMEM);
    cudaFuncSetAttribute(k_decoder,    cudaFuncAttributeMaxDynamicSharedMemorySize, DC_SMEM);

    // CSR build + one-time weight split
    k_zerowt<<<(NN + 255) / 256, 256>>>(W1l, W1r, W2l, W2r, Wm1, Wm2);
    k_count<<<(NE + 255) / 256, 256>>>(ei);
    k_scan<<<SCAN_NB, 1024>>>();
    k_scatter<<<(NE + 255) / 256, 256>>>(ei);

    // layer 1: h = relu(aggr@W1l^T + b1l + x@W1r^T)
    k_aggr<<<(NN * 32 + 255) / 256, 256>>>(x, 1);
    k_gemm_layer<<<(NN + 127) / 128, 256, LY_SMEM>>>(x, b1l, 1);
    // layer 2: z = aggr(h)@W2l^T + b2l + h@W2r^T
    k_aggr<<<(NN * 32 + 255) / 256, 256>>>(x, 2);
    k_gemm_layer<<<(NN + 127) / 128, 256, LY_SMEM>>>(x, b2l, 2);
    // decoder
    k_decoder<<<(NP + 127) / 128, 256, DC_SMEM>>>(pairs, bm1, bm2, Wm3, bm3, out);
}

// round 17
// speedup vs baseline: 2.2636x; 1.1418x over previous
#include <cuda_runtime.h>
#include <cuda_fp16.h>
#include <mma.h>
#include <cstdint>

using namespace nvcuda;

#define NN 100000
#define NE 1600000
#define NP 500000
#define D  128
#define LH  136   // half pitch, K=128 tiles (272B rows; LDSM conflict-free)
#define LF  132   // float pitch, staging
#define LT  68    // float pitch, final staging
#define SCAN_NB 98

// ---------------- fp16 split helpers ----------------
__device__ __forceinline__ void split1h(float v, __half& h, __half& l) {
    h = __float2half_rn(v);
    l = __float2half_rn(v - __half2float(h));
}
__device__ __forceinline__ void split4h(float4 v, uint2& hq, uint2& lq) {
    __half h0, h1, h2, h3, l0, l1, l2, l3;
    split1h(v.x, h0, l0); split1h(v.y, h1, l1);
    split1h(v.z, h2, l2); split1h(v.w, h3, l3);
    hq.x = (uint32_t)__half_as_ushort(h0) | ((uint32_t)__half_as_ushort(h1) << 16);
    hq.y = (uint32_t)__half_as_ushort(h2) | ((uint32_t)__half_as_ushort(h3) << 16);
    lq.x = (uint32_t)__half_as_ushort(l0) | ((uint32_t)__half_as_ushort(l1) << 16);
    lq.y = (uint32_t)__half_as_ushort(l2) | ((uint32_t)__half_as_ushort(l3) << 16);
}

// ---------------- scratch ----------------
__device__ int   g_cnt[NN];
__device__ int   g_rowptr[NN + 1];
__device__ int   g_pos[NN];
__device__ float g_inv[NN];
__device__ int   g_srcs[NE];
__device__ float g_aggr[(size_t)NN * D];
__device__ float g_h[(size_t)NN * D];
__device__ float g_z[(size_t)NN * D];
__device__ volatile int g_blk_val[SCAN_NB];
__device__ volatile int g_blk_flag[SCAN_NB];
__device__ __half g_w1h[128 * 256], g_w1l[128 * 256];
__device__ __half g_w2h[128 * 256], g_w2l[128 * 256];
__device__ __half g_wm1h[128 * 128], g_wm1l[128 * 128];
__device__ __half g_wm2h[64 * 128],  g_wm2l[64 * 128];

// ---------------- merged zero + weight split ----------------
__global__ void k_zerowt(const float* __restrict__ W1l, const float* __restrict__ W1r,
                         const float* __restrict__ W2l, const float* __restrict__ W2r,
                         const float* __restrict__ Wm1, const float* __restrict__ Wm2) {
    int i = blockIdx.x * blockDim.x + threadIdx.x;
    if (i < NN) g_cnt[i] = 0;
    if (i < SCAN_NB) g_blk_flag[i] = 0;
    if (i < 128 * 256) {
        int j = i >> 8, k = i & 255;
        float v1 = (k < 128) ? W1l[j * 128 + k] : W1r[j * 128 + (k - 128)];
        float v2 = (k < 128) ? W2l[j * 128 + k] : W2r[j * 128 + (k - 128)];
        split1h(v1, g_w1h[i], g_w1l[i]);
        split1h(v2, g_w2h[i], g_w2l[i]);
    }
    if (i < 128 * 128) split1h(Wm1[i], g_wm1h[i], g_wm1l[i]);
    if (i < 64 * 128)  split1h(Wm2[i], g_wm2h[i], g_wm2l[i]);
}

__global__ void k_count(const int* __restrict__ ei) {
    int i = blockIdx.x * blockDim.x + threadIdx.x;
    if (i < NE) atomicAdd(&g_cnt[ei[NE + i]], 1);
}

// ---------------- multi-block scan with chained lookback ----------------
__global__ void __launch_bounds__(1024, 1) k_scan() {
    __shared__ int sw[32];
    __shared__ int s_pfx;
    int b = blockIdx.x, tid = threadIdx.x;
    int i = b * 1024 + tid;
    int lane = tid & 31, wid = tid >> 5;
    int v = (i < NN) ? g_cnt[i] : 0;
    int x = v;
#pragma unroll
    for (int o = 1; o < 32; o <<= 1) {
        int t = __shfl_up_sync(0xffffffffu, x, o);
        if (lane >= o) x += t;
    }
    if (lane == 31) sw[wid] = x;
    __syncthreads();
    if (wid == 0) {
        int y = sw[lane];
#pragma unroll
        for (int o = 1; o < 32; o <<= 1) {
            int t = __shfl_up_sync(0xffffffffu, y, o);
            if (lane >= o) y += t;
        }
        sw[lane] = y;
    }
    __syncthreads();
    int incl = x + (wid > 0 ? sw[wid - 1] : 0);
    int total = sw[31];
    if (tid == 0) {
        int pfx = 0;
        if (b > 0) {
            while (g_blk_flag[b - 1] == 0) { }
            __threadfence();
            pfx = g_blk_val[b - 1];
        }
        s_pfx = pfx;
        g_blk_val[b] = pfx + total;
        __threadfence();
        g_blk_flag[b] = 1;
    }
    __syncthreads();
    int pfx = s_pfx;
    int excl = pfx + incl - v;
    if (i < NN) {
        g_rowptr[i] = excl;
        g_pos[i]    = excl;
        g_inv[i]    = 1.0f / (float)(v > 0 ? v : 1);
        if (i == NN - 1) g_rowptr[NN] = excl + v;
    }
}

__global__ void k_scatter(const int* __restrict__ ei) {
    int i = blockIdx.x * blockDim.x + threadIdx.x;
    if (i < NE) {
        int dst = ei[NE + i];
        int src = ei[i];
        int p = atomicAdd(&g_pos[dst], 1);
        g_srcs[p] = src;
    }
}

// ---------------- mean aggregation ----------------
__global__ void k_aggr(const float* __restrict__ x, int layer) {
    const float* __restrict__ feat = (layer == 1) ? x : g_h;
    int warp = (blockIdx.x * blockDim.x + threadIdx.x) >> 5;
    int lane = threadIdx.x & 31;
    if (warp >= NN) return;
    int beg = g_rowptr[warp], end = g_rowptr[warp + 1];
    float4 acc = make_float4(0.f, 0.f, 0.f, 0.f);
    int e = beg;
    for (; e + 4 <= end; e += 4) {
        int s0 = g_srcs[e], s1 = g_srcs[e + 1], s2 = g_srcs[e + 2], s3 = g_srcs[e + 3];
        float4 v0 = *(const float4*)&feat[(size_t)s0 * D + lane * 4];
        float4 v1 = *(const float4*)&feat[(size_t)s1 * D + lane * 4];
        float4 v2 = *(const float4*)&feat[(size_t)s2 * D + lane * 4];
        float4 v3 = *(const float4*)&feat[(size_t)s3 * D + lane * 4];
        acc.x += v0.x; acc.y += v0.y; acc.z += v0.z; acc.w += v0.w;
        acc.x += v1.x; acc.y += v1.y; acc.z += v1.z; acc.w += v1.w;
        acc.x += v2.x; acc.y += v2.y; acc.z += v2.z; acc.w += v2.w;
        acc.x += v3.x; acc.y += v3.y; acc.z += v3.z; acc.w += v3.w;
    }
    for (; e < end; e++) {
        int s = g_srcs[e];
        float4 v = *(const float4*)&feat[(size_t)s * D + lane * 4];
        acc.x += v.x; acc.y += v.y; acc.z += v.z; acc.w += v.w;
    }
    float inv = g_inv[warp];
    acc.x *= inv; acc.y *= inv; acc.z *= inv; acc.w *= inv;
    *(float4*)&g_aggr[(size_t)warp * D + lane * 4] = acc;
}

// ================= layer GEMM: fp16 split-3 wmma, 512 thr, M-tile 256 =================
// smem: Bh@0 [128][136]h 34816, Bl@34816 (B staged per K-phase)
//       Ah@69632 [256][136]h 69632, Al@139264  (ends 208896)
//       Sg fp32 [256][132] = 135168 aliases A region
#define LY_B  0
#define LY_A  69632
#define LY_SMEM 208896

__global__ void __launch_bounds__(512, 1)
k_gemm_layer(const float* __restrict__ x, const float* __restrict__ bias, int layer) {
    extern __shared__ char smc[];
    __half* Bh = (__half*)(smc + LY_B);
    __half* Bl = (__half*)(smc + LY_B + 34816);
    __half* Ah = (__half*)(smc + LY_A);
    __half* Al = (__half*)(smc + LY_A + 69632);
    float*  Sg = (float*)(smc + LY_A);

    const float* __restrict__ self = (layer == 1) ? x : g_h;
    const __half* __restrict__ wbh = (layer == 1) ? g_w1h : g_w2h;
    const __half* __restrict__ wbl = (layer == 1) ? g_w1l : g_w2l;
    float* __restrict__ out        = (layer == 1) ? g_h : g_z;
    const int do_relu = (layer == 1);

    int tid = threadIdx.x, wid = tid >> 5;
    int row0 = blockIdx.x * 256;
    int m0 = wid * 16;           // 16 warps x 16 rows = 256

    wmma::fragment<wmma::accumulator, 16, 16, 16, float> acc[8];
#pragma unroll
    for (int jt = 0; jt < 8; jt++) wmma::fill_fragment(acc[jt], 0.f);

    for (int ph = 0; ph < 2; ph++) {
        const float* __restrict__ A = (ph == 0) ? g_aggr : self;
        // stage B chunk [128 j][128 k] (pre-split copy; k-slice ph*128)
        for (int idx = tid * 8; idx < 128 * 128; idx += 4096) {
            int j = idx >> 7, k = idx & 127;
            *(uint4*)&Bh[j * LH + k] = *(const uint4*)&wbh[j * 256 + ph * 128 + k];
            *(uint4*)&Bl[j * LH + k] = *(const uint4*)&wbl[j * 256 + ph * 128 + k];
        }
        // stage A: rows row0..+255, k 0..127, split fp16 hi/lo
        for (int idx = tid * 4; idx < 256 * 128; idx += 2048) {
            int r = idx >> 7, k = idx & 127;
            int row = row0 + r;
            float4 v = make_float4(0.f, 0.f, 0.f, 0.f);
            if (row < NN) v = *(const float4*)&A[(size_t)row * 128 + k];
            uint2 hq, lq;
            split4h(v, hq, lq);
            *(uint2*)&Ah[r * LH + k] = hq;
            *(uint2*)&Al[r * LH + k] = lq;
        }
        __syncthreads();
        for (int kk = 0; kk < 128; kk += 16) {
            wmma::fragment<wmma::matrix_a, 16, 16, 16, __half, wmma::row_major> ah, al;
            wmma::load_matrix_sync(ah, Ah + m0 * LH + kk, LH);
            wmma::load_matrix_sync(al, Al + m0 * LH + kk, LH);
#pragma unroll
            for (int jt = 0; jt < 8; jt++) {
                wmma::fragment<wmma::matrix_b, 16, 16, 16, __half, wmma::col_major> bh, bl;
                wmma::load_matrix_sync(bh, Bh + jt * 16 * LH + kk, LH);
                wmma::load_matrix_sync(bl, Bl + jt * 16 * LH + kk, LH);
                wmma::mma_sync(acc[jt], ah, bh, acc[jt]);
                wmma::mma_sync(acc[jt], ah, bl, acc[jt]);
                wmma::mma_sync(acc[jt], al, bh, acc[jt]);
            }
        }
        __syncthreads();
    }

    // epilogue: stage fp32 (aliases A), bias+relu, store
#pragma unroll
    for (int jt = 0; jt < 8; jt++)
        wmma::store_matrix_sync(Sg + m0 * LF + jt * 16, acc[jt], LF, wmma::mem_row_major);
    __syncthreads();
    for (int idx = tid * 4; idx < 256 * 128; idx += 2048) {
        int r = idx >> 7, j = idx & 127;
        int row = row0 + r;
        if (row < NN) {
            float4 b = *(const float4*)&bias[j];
            float4 s = *(float4*)&Sg[r * LF + j];
            float4 o;
            o.x = s.x + b.x; o.y = s.y + b.y; o.z = s.z + b.z; o.w = s.w + b.w;
            if (do_relu) {
                o.x = fmaxf(o.x, 0.f); o.y = fmaxf(o.y, 0.f);
                o.z = fmaxf(o.z, 0.f); o.w = fmaxf(o.w, 0.f);
            }
            *(float4*)&out[(size_t)row * 128 + j] = o;
        }
    }
}

// ================= decoder: fp16 split-3 wmma, 512 thr =================
// warp w: m-tile = (w&7)*16, j-half = w>>3
#define DC_AH  0
#define DC_AL  34816
#define DC_B1  69632
#define DC_B2  139264
#define DC_SMEM 174080

__global__ void __launch_bounds__(512, 1)
k_decoder(const int* __restrict__ pairs,
          const float* __restrict__ bm1, const float* __restrict__ bm2,
          const float* __restrict__ wm3, const float* __restrict__ bm3,
          float* __restrict__ out) {
    extern __shared__ char smc[];
    __half* Ah  = (__half*)(smc + DC_AH);
    __half* Al  = (__half*)(smc + DC_AL);
    __half* B1h = (__half*)(smc + DC_B1);
    __half* B1l = (__half*)(smc + DC_B1 + 34816);
    __half* B2h = (__half*)(smc + DC_B2);
    __half* B2l = (__half*)(smc + DC_B2 + 17408);
    float*  Sg  = (float*)(smc + DC_B1);
    int tid = threadIdx.x, wid = tid >> 5;
    int p0 = blockIdx.x * 128;
    int m0 = (wid & 7) * 16;
    int jh = wid >> 3;           // j-half 0/1

    // stage B1 [128][128], B2 [64][128] (pre-split copies)
    for (int idx = tid * 8; idx < 128 * 128; idx += 4096) {
        int j = idx >> 7, k = idx & 127;
        *(uint4*)&B1h[j * LH + k] = *(const uint4*)&g_wm1h[j * 128 + k];
        *(uint4*)&B1l[j * LH + k] = *(const uint4*)&g_wm1l[j * 128 + k];
    }
    for (int idx = tid * 8; idx < 64 * 128; idx += 4096) {
        int j = idx >> 7, k = idx & 127;
        *(uint4*)&B2h[j * LH + k] = *(const uint4*)&g_wm2h[j * 128 + k];
        *(uint4*)&B2l[j * LH + k] = *(const uint4*)&g_wm2l[j * 128 + k];
    }
    // hp = z[i0]*z[i1] -> split-fp16 A (each thread: 1 pair-quarter of 32 k)
    {
        int p = tid >> 2;
        int d0 = (tid & 3) * 32;
        int pg = p0 + p;
        if (pg >= NP) pg = 0;
        int i0 = pairs[(size_t)pg * 2 + 0];
        int i1 = pairs[(size_t)pg * 2 + 1];
        const float* z0 = &g_z[(size_t)i0 * 128 + d0];
        const float* z1 = &g_z[(size_t)i1 * 128 + d0];
#pragma unroll
        for (int t = 0; t < 8; t++) {
            float4 a = *(const float4*)&z0[t * 4];
            float4 b = *(const float4*)&z1[t * 4];
            float4 v = make_float4(a.x * b.x, a.y * b.y, a.z * b.z, a.w * b.w);
            uint2 hq, lq;
            split4h(v, hq, lq);
            *(uint2*)&Ah[p * LH + d0 + t * 4] = hq;
            *(uint2*)&Al[p * LH + d0 + t * 4] = lq;
        }
    }
    __syncthreads();

    // GEMM1: t1 = hp @ Wm1^T ; each warp: 4 j-tiles of its half
    wmma::fragment<wmma::accumulator, 16, 16, 16, float> acc1[4];
#pragma unroll
    for (int t = 0; t < 4; t++) wmma::fill_fragment(acc1[t], 0.f);
    for (int kk = 0; kk < 128; kk += 16) {
        wmma::fragment<wmma::matrix_a, 16, 16, 16, __half, wmma::row_major> ah, al;
        wmma::load_matrix_sync(ah, Ah + m0 * LH + kk, LH);
        wmma::load_matrix_sync(al, Al + m0 * LH + kk, LH);
#pragma unroll
        for (int t = 0; t < 4; t++) {
            int jt = jh * 4 + t;
            wmma::fragment<wmma::matrix_b, 16, 16, 16, __half, wmma::col_major> bh, bl;
            wmma::load_matrix_sync(bh, B1h + jt * 16 * LH + kk, LH);
            wmma::load_matrix_sync(bl, B1l + jt * 16 * LH + kk, LH);
            wmma::mma_sync(acc1[t], ah, bh, acc1[t]);
            wmma::mma_sync(acc1[t], ah, bl, acc1[t]);
            wmma::mma_sync(acc1[t], al, bh, acc1[t]);
        }
    }
    __syncthreads();   // B1 reads done -> Sg may overwrite

#pragma unroll
    for (int t = 0; t < 4; t++)
        wmma::store_matrix_sync(Sg + m0 * LF + (jh * 4 + t) * 16, acc1[t], LF, wmma::mem_row_major);
    __syncthreads();

    // t1 = relu(Sg + bm1) -> re-split into A
    for (int idx = tid * 4; idx < 128 * 128; idx += 2048) {
        int r = idx >> 7, k = idx & 127;
        float4 b = *(const float4*)&bm1[k];
        float4 s = *(float4*)&Sg[r * LF + k];
        float4 v = make_float4(fmaxf(s.x + b.x, 0.f), fmaxf(s.y + b.y, 0.f),
                               fmaxf(s.z + b.z, 0.f), fmaxf(s.w + b.w, 0.f));
        uint2 hq, lq;
        split4h(v, hq, lq);
        *(uint2*)&Ah[r * LH + k] = hq;
        *(uint2*)&Al[r * LH + k] = lq;
    }
    __syncthreads();

    // GEMM2: t2 = t1 @ Wm2^T ; each warp: 2 j-tiles of its half
    wmma::fragment<wmma::accumulator, 16, 16, 16, float> acc2[2];
#pragma unroll
    for (int t = 0; t < 2; t++) wmma::fill_fragment(acc2[t], 0.f);
    for (int kk = 0; kk < 128; kk += 16) {
        wmma::fragment<wmma::matrix_a, 16, 16, 16, __half, wmma::row_major> ah, al;
        wmma::load_matrix_sync(ah, Ah + m0 * LH + kk, LH);
        wmma::load_matrix_sync(al, Al + m0 * LH + kk, LH);
#pragma unroll
        for (int t = 0; t < 2; t++) {
            int jt = jh * 2 + t;
            wmma::fragment<wmma::matrix_b, 16, 16, 16, __half, wmma::col_major> bh, bl;
            wmma::load_matrix_sync(bh, B2h + jt * 16 * LH + kk, LH);
            wmma::load_matrix_sync(bl, B2l + jt * 16 * LH + kk, LH);
            wmma::mma_sync(acc2[t], ah, bh, acc2[t]);
            wmma::mma_sync(acc2[t], ah, bl, acc2[t]);
            wmma::mma_sync(acc2[t], al, bh, acc2[t]);
        }
    }
    __syncthreads();
#pragma unroll
    for (int t = 0; t < 2; t++)
        wmma::store_matrix_sync(Sg + m0 * LT + (jh * 2 + t) * 16, acc2[t], LT, wmma::mem_row_major);
    __syncthreads();

    // out[p] = sum_j relu(t2[p][j]+bm2[j])*wm3[j] + bm3
    if (tid < 128) {
        int p = p0 + tid;
        float acc = bm3[0];
#pragma unroll 16
        for (int j = 0; j < 64; j++)
            acc += fmaxf(Sg[tid * LT + j] + bm2[j], 0.f) * wm3[j];
        if (p < NP) out[p] = acc;
    }
}

// ================= launch =================
extern "C" void kernel_launch(void* const* d_in, const int* in_sizes, int n_in,
                              void* d_out, int out_size) {
    const float* x     = (const float*)d_in[0];
    const int*   ei    = (const int*)d_in[1];
    const int*   pairs = (const int*)d_in[2];
    const float* W1l = (const float*)d_in[3];
    const float* b1l = (const float*)d_in[4];
    const float* W1r = (const float*)d_in[5];
    const float* W2l = (const float*)d_in[6];
    const float* b2l = (const float*)d_in[7];
    const float* W2r = (const float*)d_in[8];
    const float* Wm1 = (const float*)d_in[9];
    const float* bm1 = (const float*)d_in[10];
    const float* Wm2 = (const float*)d_in[11];
    const float* bm2 = (const float*)d_in[12];
    const float* Wm3 = (const float*)d_in[13];
    const float* bm3 = (const float*)d_in[14];
    float* out = (float*)d_out;
    (void)in_sizes; (void)n_in; (void)out_size;

    cudaFuncSetAttribute(k_gemm_layer, cudaFuncAttributeMaxDynamicSharedMemorySize, LY_SMEM);
    cudaFuncSetAttribute(k_decoder,    cudaFuncAttributeMaxDynamicSharedMemorySize, DC_SMEM);

    // CSR build + one-time weight split
    k_zerowt<<<(NN + 255) / 256, 256>>>(W1l, W1r, W2l, W2r, Wm1, Wm2);
    k_count<<<(NE + 255) / 256, 256>>>(ei);
    k_scan<<<SCAN_NB, 1024>>>();
    k_scatter<<<(NE + 255) / 256, 256>>>(ei);

    // layer 1: h = relu(aggr@W1l^T + b1l + x@W1r^T)
    k_aggr<<<(NN * 32 + 255) / 256, 256>>>(x, 1);
    k_gemm_layer<<<(NN + 255) / 256, 512, LY_SMEM>>>(x, b1l, 1);
    // layer 2: z = aggr(h)@W2l^T + b2l + h@W2r^T
    k_aggr<<<(NN * 32 + 255) / 256, 256>>>(x, 2);
    k_gemm_layer<<<(NN + 255) / 256, 512, LY_SMEM>>>(x, b2l, 2);
    // decoder
    k_decoder<<<(NP + 127) / 128, 512, DC_SMEM>>>(pairs, bm1, bm2, Wm3, bm3, out);
}